// round 11
// baseline (speedup 1.0000x reference)
#include <cuda_runtime.h>

// GMP: out[b,j] = sum_{i=0..7} xc[b,j+i-7] * ( W[i,0]
//                 + sum_{m=0..7} sum_{d=0..2} W[i,1+3m+d] * |xc[b,j+i+m-14]|^(d+1) )
// Horner in amplitude only:  sum_d c_d a^(d+1) = a*(c1 + a*(c2 + a*c3))
// Gain loop packed 2-wide with fma.rn.f32x2 over adjacent output pairs.

#define PER   8
#define MTAP  8
#define KDEG  3
#define WROW  (1 + KDEG * MTAP)   // 25

typedef unsigned long long u64;

__device__ __forceinline__ u64 pack2(float lo, float hi) {
    u64 r; asm("mov.b64 %0,{%1,%2};" : "=l"(r) : "f"(lo), "f"(hi)); return r;
}
__device__ __forceinline__ u64 ffma2(u64 a, u64 b, u64 c) {
    u64 d; asm("fma.rn.f32x2 %0,%1,%2,%3;" : "=l"(d) : "l"(a), "l"(b), "l"(c)); return d;
}
__device__ __forceinline__ void unpack2(u64 v, float& lo, float& hi) {
    asm("mov.b64 {%0,%1},%2;" : "=f"(lo), "=f"(hi) : "l"(v));
}

__global__ __launch_bounds__(256)
void gmp_kernel(const float2* __restrict__ x,
                const float*  __restrict__ W,
                float2* __restrict__ out,
                int T)
{
    // coefficients pre-duplicated into (c,c) 64-bit pairs for packed FMA
    __shared__ u64 sWp[MTAP * WROW];
    if (threadIdx.x < MTAP * WROW) {
        float c = W[threadIdx.x];
        sWp[threadIdx.x] = pack2(c, c);
    }
    __syncthreads();

    const int tid    = blockIdx.x * blockDim.x + threadIdx.x;
    const int chunks = T / PER;                 // 2048
    const int row    = tid / chunks;
    const int col    = tid % chunks;
    const float2* xr   = x   + (long long)row * T;
    float2*       orow = out + (long long)row * T;
    const int j0   = col * PER;
    const int base = j0 - 14;

    // amplitude window a[k] <-> position j0-14+k, k=0..21
    float a[PER + 14];
    float xwr[PER + 7], xwi[PER + 7];           // xc at j0-7 .. j0+7
    #pragma unroll
    for (int k = 0; k < PER + 14; ++k) {
        int p = base + k;
        float2 v = (p >= 0) ? xr[p] : make_float2(0.0f, 0.0f);
        float m2 = fmaf(v.x, v.x, v.y * v.y);
        asm("sqrt.approx.f32 %0,%1;" : "=f"(a[k]) : "f"(m2));
        if (k >= 7) { xwr[k - 7] = v.x; xwi[k - 7] = v.y; }
    }

    // both-parity adjacent pairs P[k] = (a[k], a[k+1]), k = 0..20
    u64 P[PER + 13];
    #pragma unroll
    for (int k = 0; k < PER + 13; ++k) P[k] = pack2(a[k], a[k + 1]);

    float outr[PER], outi[PER];
    #pragma unroll
    for (int jj = 0; jj < PER; ++jj) { outr[jj] = 0.0f; outi[jj] = 0.0f; }

    #pragma unroll
    for (int i = 0; i < MTAP; ++i) {
        u64 gp[PER / 2];                        // packed gains for (2q, 2q+1)
        const u64 c0p = sWp[i * WROW];
        #pragma unroll
        for (int q = 0; q < PER / 2; ++q) gp[q] = c0p;

        #pragma unroll
        for (int m = 0; m < MTAP; ++m) {
            const u64 c1p = sWp[i * WROW + 1 + m * KDEG + 0];
            const u64 c2p = sWp[i * WROW + 1 + m * KDEG + 1];
            const u64 c3p = sWp[i * WROW + 1 + m * KDEG + 2];
            #pragma unroll
            for (int q = 0; q < PER / 2; ++q) {
                const u64 A = P[2 * q + i + m];     // amp pair at j+i+m-14
                u64 h = ffma2(c3p, A, c2p);
                h     = ffma2(h,   A, c1p);
                gp[q] = ffma2(h,   A, gp[q]);       // g += a*(c1 + a*(c2 + a*c3))
            }
        }

        #pragma unroll
        for (int q = 0; q < PER / 2; ++q) {
            float g0, g1; unpack2(gp[q], g0, g1);
            const int jj = 2 * q;
            const int n  = jj + i;                  // x position j+i-7
            outr[jj]     = fmaf(g0, xwr[n],     outr[jj]);
            outi[jj]     = fmaf(g0, xwi[n],     outi[jj]);
            outr[jj + 1] = fmaf(g1, xwr[n + 1], outr[jj + 1]);
            outi[jj + 1] = fmaf(g1, xwi[n + 1], outi[jj + 1]);
        }
    }

    #pragma unroll
    for (int jj = 0; jj < PER; ++jj)
        orow[j0 + jj] = make_float2(outr[jj], outi[jj]);
}

extern "C" void kernel_launch(void* const* d_in, const int* in_sizes, int n_in,
                              void* d_out, int out_size)
{
    const float2* x = (const float2*)d_in[0];   // (B, T, 2) f32
    const float*  W = (const float*)d_in[2];    // (8, 25) f32
    float2* out = (float2*)d_out;

    const int B = 64, T = 16384;
    const int totalThreads = B * (T / PER);     // 131072
    const int threads = 256;
    const int blocks  = totalThreads / threads; // 512
    gmp_kernel<<<blocks, threads>>>(x, W, out, T);
}